// round 10
// baseline (speedup 1.0000x reference)
#include <cuda_runtime.h>
#include <cuda_fp16.h>
#include <cstdint>
#include <cstddef>

#define B_  64
#define S_  512
#define E_  1024
#define H_  1024
#define NG  4096
#define NCTA 128

// ---------------- device scratch ----------------
__device__ float  g_xg[(size_t)S_ * B_ * NG];     // [t][b][n] fp32
__device__ __half g_xh[(size_t)B_ * S_ * E_];     // x in fp16
__device__ __half g_wh[(size_t)NG * E_];          // Wx in fp16, [gate-major n][k]
__device__ __half g_hh[2][B_ * H_];               // hidden state fp16, [b][k]
__device__ unsigned g_bar_count = 0;
__device__ unsigned g_bar_gen   = 0;

// ---------------- helpers ----------------
__device__ __forceinline__ uint32_t smem_u32(const void* p) {
    uint32_t a;
    asm("{ .reg .u64 t; cvta.to.shared.u64 t, %1; cvt.u32.u64 %0, t; }" : "=r"(a) : "l"(p));
    return a;
}
__device__ __forceinline__ void cpa16(uint32_t saddr, const void* g) {
    asm volatile("cp.async.cg.shared.global [%0], [%1], 16;" :: "r"(saddr), "l"(g) : "memory");
}
__device__ __forceinline__ void cpa_commit() {
    asm volatile("cp.async.commit_group;" ::: "memory");
}
template<int N> __device__ __forceinline__ void cpa_wait() {
    asm volatile("cp.async.wait_group %0;" :: "n"(N) : "memory");
}
__device__ __forceinline__ void ldmx4(uint32_t* r, uint32_t addr) {
    asm volatile("ldmatrix.sync.aligned.m8n8.x4.shared.b16 {%0,%1,%2,%3}, [%4];"
        : "=r"(r[0]), "=r"(r[1]), "=r"(r[2]), "=r"(r[3]) : "r"(addr));
}
__device__ __forceinline__ void mma16(float* d, const uint32_t* a, const uint32_t* b) {
    asm("mma.sync.aligned.m16n8k16.row.col.f32.f16.f16.f32 "
        "{%0,%1,%2,%3}, {%4,%5,%6,%7}, {%8,%9}, {%0,%1,%2,%3};"
        : "+f"(d[0]), "+f"(d[1]), "+f"(d[2]), "+f"(d[3])
        : "r"(a[0]), "r"(a[1]), "r"(a[2]), "r"(a[3]), "r"(b[0]), "r"(b[1]));
}
__device__ __forceinline__ float sigm(float z) { return 1.f / (1.f + expf(-z)); }

__device__ __forceinline__ void grid_barrier() {
    __syncthreads();
    if (threadIdx.x == 0) {
        __threadfence();
        unsigned gen = *(volatile unsigned*)&g_bar_gen;
        if (atomicAdd(&g_bar_count, 1u) == NCTA - 1) {
            atomicExch(&g_bar_count, 0u);
            __threadfence();
            atomicAdd(&g_bar_gen, 1u);
        } else {
            while (*(volatile unsigned*)&g_bar_gen == gen) __nanosleep(32);
        }
        __threadfence();
    }
    __syncthreads();
}

// ===========================================================================
// Kernel 0: convert x and Wx (x-part columns) to fp16 scratch.
// ===========================================================================
__global__ void convert_h(
    const float* __restrict__ x,
    const float* __restrict__ Wf, const float* __restrict__ Wi,
    const float* __restrict__ Wc, const float* __restrict__ Wo)
{
    const int stride = gridDim.x * blockDim.x;
    const int i0 = blockIdx.x * blockDim.x + threadIdx.x;
    const int NX = B_ * S_ * E_ / 2;
    for (int i = i0; i < NX; i += stride) {
        float2 v = *(const float2*)(x + (size_t)2 * i);
        ((__half2*)g_xh)[i] = __floats2half2_rn(v.x, v.y);
    }
    const int NW = NG * E_ / 2;
    for (int i = i0; i < NW; i += stride) {
        int n = i >> 9, k2 = i & 511;
        const float* Ws = (n < 1024) ? Wf : (n < 2048) ? Wi : (n < 3072) ? Wc : Wo;
        float2 v = *(const float2*)(Ws + (size_t)(n & 1023) * 2048 + k2 * 2);
        ((__half2*)g_wh)[i] = __floats2half2_rn(v.x, v.y);
    }
}

// ===========================================================================
// Phase 1: Xg = x @ Wx^T (fp16 mma, ldmatrix, cp.async 3-stage). Unchanged.
// ===========================================================================
#define P1_STAGE 36864
#define P1_SMEM  (3 * P1_STAGE)

__device__ __forceinline__ void p1_issue(uint32_t sb, int m0, int n0, int k0, int tid) {
    const int r = tid >> 3, c = tid & 7;
#pragma unroll
    for (int j = 0; j < 4; j++) {
        int rr = r + j * 32;
        cpa16(sb + rr * 144 + c * 16,         g_xh + (size_t)(m0 + rr) * E_ + k0 + c * 8);
        cpa16(sb + 18432 + rr * 144 + c * 16, g_wh + (size_t)(n0 + rr) * E_ + k0 + c * 8);
    }
    cpa_commit();
}

__global__ void __launch_bounds__(256, 2) xgemm_h()
{
    extern __shared__ char sm[];
    const uint32_t smb = smem_u32(sm);

    const int tid = threadIdx.x;
    const int wid = tid >> 5, lane = tid & 31;
    const int gid = lane >> 2, tg = lane & 3;
    const int wm = wid >> 2, wn = wid & 3;
    const int m0 = blockIdx.y * 128;
    const int n0 = blockIdx.x * 128;

    uint32_t laneA[4], laneB[2];
#pragma unroll
    for (int mi = 0; mi < 4; mi++)
        laneA[mi] = (wm * 64 + mi * 16 + ((lane >> 3) & 1) * 8 + (lane & 7)) * 144
                  + (lane >> 4) * 16;
#pragma unroll
    for (int p = 0; p < 2; p++)
        laneB[p] = 18432
                 + (wn * 32 + p * 16 + (lane >> 4) * 8 + (lane & 7)) * 144
                 + ((lane >> 3) & 1) * 16;

    float acc[4][4][4];
#pragma unroll
    for (int i = 0; i < 4; i++)
#pragma unroll
        for (int j = 0; j < 4; j++)
#pragma unroll
            for (int k = 0; k < 4; k++) acc[i][j][k] = 0.f;

    p1_issue(smb, m0, n0, 0, tid);
    p1_issue(smb + P1_STAGE, m0, n0, 64, tid);

    int st = 0;
    for (int ch = 0; ch < 16; ch++) {
        if (ch < 15) cpa_wait<1>(); else cpa_wait<0>();
        __syncthreads();
        if (ch + 2 < 16) {
            int st2 = st + 2; if (st2 >= 3) st2 -= 3;
            p1_issue(smb + st2 * P1_STAGE, m0, n0, (ch + 2) * 64, tid);
        }
        const uint32_t sb = smb + st * P1_STAGE;
#pragma unroll
        for (int kk = 0; kk < 4; kk++) {
            uint32_t a[4][4], b[2][4];
#pragma unroll
            for (int mi = 0; mi < 4; mi++) ldmx4(a[mi], sb + laneA[mi] + kk * 32);
#pragma unroll
            for (int p = 0; p < 2; p++)   ldmx4(b[p],  sb + laneB[p] + kk * 32);
#pragma unroll
            for (int mi = 0; mi < 4; mi++)
#pragma unroll
                for (int ni = 0; ni < 4; ni++)
                    mma16(acc[mi][ni], a[mi], b[ni >> 1] + (ni & 1) * 2);
        }
        if (++st >= 3) st -= 3;
    }

#pragma unroll
    for (int mi = 0; mi < 4; mi++) {
        int row = m0 + wm * 64 + mi * 16 + gid;
        int b = row >> 9, t = row & (S_ - 1);
#pragma unroll
        for (int ni = 0; ni < 4; ni++) {
            int col = n0 + wn * 32 + ni * 8 + tg * 2;
            float* p0 = g_xg + ((size_t)t * B_ + b) * NG + col;
            float* p1 = g_xg + ((size_t)(t + 8) * B_ + b) * NG + col;
            *(float2*)p0 = make_float2(acc[mi][ni][0], acc[mi][ni][1]);
            *(float2*)p1 = make_float2(acc[mi][ni][2], acc[mi][ni][3]);
        }
    }
}

// ===========================================================================
// Phase 2: persistent scan, fp16 mma. ROLE SWAP: W = A operand, resident in
// REGISTERS (64 regs/warp, loaded once). h = B operand, staged per step.
// 8 warps = 2 (gate-col halves gh) x 4 (K-quarters kg); split-K via SMEM.
// ===========================================================================
#define HROW    2064                       // bytes per SMEM h row (1032 halves)
#define HB_OFF  0                          // h buffer [64][HROW] = 132096 B
#define RED_OFF 132096                     // 3 x [32][66] f32    = 25344 B
#define ZB_OFF  157440                     // [32][66] f32        = 8448 B
#define CS_OFF  165888                     // 2048 B
#define BS_OFF  167936                     // 128 B
#define P2_SMEM 168064

template<int G>
__device__ __forceinline__ void p2_quarter(
    const uint32_t laneH[4], uint32_t kbase, const uint32_t wfr[16][4],
    float acc[8][4], int kg)
{
    cpa_wait<G>();
    asm volatile("bar.sync %0, 64;" :: "r"(kg + 1) : "memory");
#pragma unroll
    for (int ksl = 0; ksl < 4; ksl++) {
        const int ks = (3 - G) * 4 + ksl;
        const uint32_t koff = kbase + ks * 32;
#pragma unroll
        for (int j = 0; j < 4; j++) {
            uint32_t bb[4];
            ldmx4(bb, laneH[j] + koff);
            mma16(acc[2 * j],     wfr[ks], bb);
            mma16(acc[2 * j + 1], wfr[ks], bb + 2);
        }
    }
}

__global__ void __launch_bounds__(256, 1) lstm_seq_h(
    const float* __restrict__ Wf, const float* __restrict__ bf,
    const float* __restrict__ Wi, const float* __restrict__ bi,
    const float* __restrict__ Wc, const float* __restrict__ bc,
    const float* __restrict__ Wo, const float* __restrict__ bo,
    float* __restrict__ out)
{
    extern __shared__ char sm[];
    float* red = (float*)(sm + RED_OFF);
    float* zbf = (float*)(sm + ZB_OFF);
    float* csm = (float*)(sm + CS_OFF);
    float* bsm = (float*)(sm + BS_OFF);

    const int tid = threadIdx.x;
    const int wid = tid >> 5, lane = tid & 31;
    const int gid = lane >> 2, tg = lane & 3;
    const int gh = wid & 1;                  // gate-col half (16 cols)
    const int kg = wid >> 1;                 // K quarter (256 k)
    const int cta = blockIdx.x;
    const float* Wp[4] = {Wf, Wi, Wc, Wo};
    const float* bp[4] = {bf, bi, bc, bo};

    const uint32_t hbB = smem_u32(sm + HB_OFF);

    // ---- one-time: Wh slice -> SMEM (rows n=0..31) -> ldmatrix -> registers
    for (int idx = tid; idx < 32 * 512; idx += 256) {
        int n = idx >> 9, k2 = idx & 511;
        float2 v = *(const float2*)(Wp[n >> 3] + (size_t)(cta * 8 + (n & 7)) * 2048 + 1024 + k2 * 2);
        *(__half2*)(sm + HB_OFF + n * HROW + k2 * 4) = __floats2half2_rn(v.x, v.y);
    }
    __syncthreads();
    uint32_t wfr[16][4];
    {
        const uint32_t aW = hbB
            + (gh * 16 + (lane & 7) + ((lane >> 3) & 1) * 8) * HROW + (lane >> 4) * 16;
#pragma unroll
        for (int ks = 0; ks < 16; ks++)
            ldmx4(wfr[ks], aW + (kg * 16 + ks) * 32);
    }
    if (tid < 32) bsm[tid] = bp[tid >> 3][cta * 8 + (tid & 7)];
    for (int i = tid; i < 512; i += 256) {
        csm[i] = 0.f;
        g_hh[0][(i >> 3) * H_ + cta * 8 + (i & 7)] = __float2half(0.f);
    }
    __syncthreads();
    grid_barrier();

    // per-lane B (h) ldmatrix bases for the 4 n16 groups
    uint32_t laneH[4];
#pragma unroll
    for (int j = 0; j < 4; j++)
        laneH[j] = hbB + (j * 16 + (lane >> 4) * 8 + (lane & 7)) * HROW
                 + ((lane >> 3) & 1) * 16;
    const uint32_t kbase = (uint32_t)(kg * 16) * 32;
    const int u = gh * 32 + lane;            // 0..63 within the kg pair

    for (int t = 0; t < S_; t++) {
        const __half* hcur = g_hh[t & 1];

        // stage this warp-pair's K quarter in 4 commit groups (8 KB each)
#pragma unroll
        for (int g4 = 0; g4 < 4; g4++) {
#pragma unroll
            for (int jj = 0; jj < 8; jj++) {
                int idx = u + jj * 64;
                int row = idx >> 3, cc = idx & 7;
                cpa16(hbB + row * HROW + kg * 512 + g4 * 128 + cc * 16,
                      hcur + row * H_ + kg * 256 + g4 * 64 + cc * 8);
            }
            cpa_commit();
        }

        float acc[8][4];
#pragma unroll
        for (int i = 0; i < 8; i++)
#pragma unroll
            for (int k = 0; k < 4; k++) acc[i][k] = 0.f;

        p2_quarter<3>(laneH, kbase, wfr, acc, kg);
        p2_quarter<2>(laneH, kbase, wfr, acc, kg);
        p2_quarter<1>(laneH, kbase, wfr, acc, kg);
        p2_quarter<0>(laneH, kbase, wfr, acc, kg);

        // ---- split-K reduction through SMEM
        const int row0 = gh * 16 + gid;
        if (kg != 0) {
            float* rp = red + (kg - 1) * 32 * 66;
#pragma unroll
            for (int j = 0; j < 4; j++)
#pragma unroll
                for (int p = 0; p < 2; p++) {
                    int nt = 2 * j + p;
                    int cb = j * 16 + p * 8 + tg * 2;
                    *(float2*)&rp[row0 * 66 + cb]       = make_float2(acc[nt][0], acc[nt][1]);
                    *(float2*)&rp[(row0 + 8) * 66 + cb] = make_float2(acc[nt][2], acc[nt][3]);
                }
        }
        __syncthreads();
        if (kg == 0) {
#pragma unroll
            for (int j = 0; j < 4; j++)
#pragma unroll
                for (int p = 0; p < 2; p++) {
                    int nt = 2 * j + p;
                    int cb = j * 16 + p * 8 + tg * 2;
                    float2 z01 = make_float2(acc[nt][0], acc[nt][1]);
                    float2 z23 = make_float2(acc[nt][2], acc[nt][3]);
#pragma unroll
                    for (int q = 0; q < 3; q++) {
                        float2 a  = *(float2*)&red[(q * 32 + row0) * 66 + cb];
                        float2 b2 = *(float2*)&red[(q * 32 + row0 + 8) * 66 + cb];
                        z01.x += a.x;  z01.y += a.y;
                        z23.x += b2.x; z23.y += b2.y;
                    }
                    *(float2*)&zbf[row0 * 66 + cb]       = z01;
                    *(float2*)&zbf[(row0 + 8) * 66 + cb] = z23;
                }
        }
        __syncthreads();

        // ---- gate math; c stays in SMEM; h -> fp16 global + fp32 output
        __half* hnext = g_hh[(t + 1) & 1];
        for (int i = tid; i < 512; i += 256) {
            int b = i >> 3, r = i & 7;
            const float* xgb = g_xg + ((size_t)t * B_ + b) * NG + cta * 8 + r;
            float zf = zbf[r * 66 + b]        + bsm[r]      + __ldg(xgb);
            float zi = zbf[(8 + r) * 66 + b]  + bsm[8 + r]  + __ldg(xgb + 1024);
            float zg = zbf[(16 + r) * 66 + b] + bsm[16 + r] + __ldg(xgb + 2048);
            float zo = zbf[(24 + r) * 66 + b] + bsm[24 + r] + __ldg(xgb + 3072);
            float cc = sigm(zf) * csm[i] + sigm(zi) * tanhf(zg);
            csm[i] = cc;
            float h = sigm(zo) * tanhf(cc);
            int hc = cta * 8 + r;
            hnext[b * H_ + hc] = __float2half(h);
            out[((size_t)b * S_ + t) * H_ + hc] = h;
            if (t == S_ - 1) {
                out[(size_t)B_ * S_ * H_ + b * H_ + hc] = h;                    // hT
                out[(size_t)B_ * S_ * H_ + (size_t)B_ * H_ + b * H_ + hc] = cc; // cT
            }
        }
        grid_barrier();
    }
}

// ===========================================================================
extern "C" void kernel_launch(void* const* d_in, const int* in_sizes, int n_in,
                              void* d_out, int out_size) {
    const float* x  = (const float*)d_in[0];
    const float* Wf = (const float*)d_in[1];
    const float* bf = (const float*)d_in[2];
    const float* Wi = (const float*)d_in[3];
    const float* bi = (const float*)d_in[4];
    const float* Wc = (const float*)d_in[5];
    const float* bc = (const float*)d_in[6];
    const float* Wo = (const float*)d_in[7];
    const float* bo = (const float*)d_in[8];
    float* out = (float*)d_out;

    convert_h<<<1024, 256>>>(x, Wf, Wi, Wc, Wo);

    cudaFuncSetAttribute(xgemm_h, cudaFuncAttributeMaxDynamicSharedMemorySize, P1_SMEM);
    dim3 g1(NG / 128, (B_ * S_) / 128);            // (32, 256)
    xgemm_h<<<g1, 256, P1_SMEM>>>();

    cudaFuncSetAttribute(lstm_seq_h, cudaFuncAttributeMaxDynamicSharedMemorySize, P2_SMEM);
    lstm_seq_h<<<NCTA, 256, P2_SMEM>>>(Wf, bf, Wi, bi, Wc, bc, Wo, bo, out);
}

// round 11
// speedup vs baseline: 1.4080x; 1.4080x over previous
#include <cuda_runtime.h>
#include <cuda_fp16.h>
#include <cstdint>
#include <cstddef>

#define B_  64
#define S_  512
#define E_  1024
#define H_  1024
#define NG  4096
#define NCTA 128

// ---------------- device scratch ----------------
__device__ float  g_xg[(size_t)S_ * B_ * NG];     // [t][b][n] fp32
__device__ __half g_xh[(size_t)B_ * S_ * E_];     // x in fp16
__device__ __half g_wh[(size_t)NG * E_];          // Wx in fp16, [gate-major n][k]
__device__ __half g_hh[2][B_ * H_];               // hidden state fp16, [b][k]
__device__ unsigned g_bar_count = 0;
__device__ unsigned g_bar_gen   = 0;
__device__ unsigned g_flags[NCTA * 64];           // per-CTA arrival flags, 256B stride

// ---------------- helpers ----------------
__device__ __forceinline__ uint32_t smem_u32(const void* p) {
    uint32_t a;
    asm("{ .reg .u64 t; cvta.to.shared.u64 t, %1; cvt.u32.u64 %0, t; }" : "=r"(a) : "l"(p));
    return a;
}
__device__ __forceinline__ void cpa16(uint32_t saddr, const void* g) {
    asm volatile("cp.async.cg.shared.global [%0], [%1], 16;" :: "r"(saddr), "l"(g) : "memory");
}
__device__ __forceinline__ void cpa_commit() {
    asm volatile("cp.async.commit_group;" ::: "memory");
}
template<int N> __device__ __forceinline__ void cpa_wait() {
    asm volatile("cp.async.wait_group %0;" :: "n"(N) : "memory");
}
__device__ __forceinline__ void ldmx4(uint32_t* r, uint32_t addr) {
    asm volatile("ldmatrix.sync.aligned.m8n8.x4.shared.b16 {%0,%1,%2,%3}, [%4];"
        : "=r"(r[0]), "=r"(r[1]), "=r"(r[2]), "=r"(r[3]) : "r"(addr));
}
__device__ __forceinline__ void mma16(float* d, const uint32_t* a, const uint32_t* b) {
    asm("mma.sync.aligned.m16n8k16.row.col.f32.f16.f16.f32 "
        "{%0,%1,%2,%3}, {%4,%5,%6,%7}, {%8,%9}, {%0,%1,%2,%3};"
        : "+f"(d[0]), "+f"(d[1]), "+f"(d[2]), "+f"(d[3])
        : "r"(a[0]), "r"(a[1]), "r"(a[2]), "r"(a[3]), "r"(b[0]), "r"(b[1]));
}
__device__ __forceinline__ float sigm(float z) { return 1.f / (1.f + expf(-z)); }

// Atomic barrier — used only twice at init (replay-safe, proven).
__device__ __forceinline__ void grid_barrier() {
    __syncthreads();
    if (threadIdx.x == 0) {
        __threadfence();
        unsigned gen = *(volatile unsigned*)&g_bar_gen;
        if (atomicAdd(&g_bar_count, 1u) == NCTA - 1) {
            atomicExch(&g_bar_count, 0u);
            __threadfence();
            atomicAdd(&g_bar_gen, 1u);
        } else {
            while (*(volatile unsigned*)&g_bar_gen == gen) __nanosleep(32);
        }
        __threadfence();
    }
    __syncthreads();
}

// Flag barrier — no atomics; distinct-address stores + MLP polling.
__device__ __forceinline__ void grid_barrier_flag(int cta, unsigned tval) {
    __syncthreads();
    if (threadIdx.x == 0) {
        __threadfence();
        *(volatile unsigned*)&g_flags[cta * 64] = tval;   // release arrival
    }
    if (threadIdx.x < 32) {
        int need = 0xF;
        const int base = threadIdx.x * 4;
        while (need) {
#pragma unroll
            for (int j = 0; j < 4; j++) {
                if (need & (1 << j)) {
                    if (*(volatile unsigned*)&g_flags[(base + j) * 64] >= tval)
                        need &= ~(1 << j);
                }
            }
            if (need) __nanosleep(32);
        }
        __threadfence();                                   // acquire
    }
    __syncthreads();
}

// ===========================================================================
// Kernel 0: convert x and Wx (x-part columns) to fp16 scratch.
// ===========================================================================
__global__ void convert_h(
    const float* __restrict__ x,
    const float* __restrict__ Wf, const float* __restrict__ Wi,
    const float* __restrict__ Wc, const float* __restrict__ Wo)
{
    const int stride = gridDim.x * blockDim.x;
    const int i0 = blockIdx.x * blockDim.x + threadIdx.x;
    const int NX = B_ * S_ * E_ / 2;
    for (int i = i0; i < NX; i += stride) {
        float2 v = *(const float2*)(x + (size_t)2 * i);
        ((__half2*)g_xh)[i] = __floats2half2_rn(v.x, v.y);
    }
    const int NW = NG * E_ / 2;
    for (int i = i0; i < NW; i += stride) {
        int n = i >> 9, k2 = i & 511;
        const float* Ws = (n < 1024) ? Wf : (n < 2048) ? Wi : (n < 3072) ? Wc : Wo;
        float2 v = *(const float2*)(Ws + (size_t)(n & 1023) * 2048 + k2 * 2);
        ((__half2*)g_wh)[i] = __floats2half2_rn(v.x, v.y);
    }
}

// ===========================================================================
// Phase 1: Xg = x @ Wx^T (fp16 mma, ldmatrix, cp.async 3-stage). Unchanged.
// ===========================================================================
#define P1_STAGE 36864
#define P1_SMEM  (3 * P1_STAGE)

__device__ __forceinline__ void p1_issue(uint32_t sb, int m0, int n0, int k0, int tid) {
    const int r = tid >> 3, c = tid & 7;
#pragma unroll
    for (int j = 0; j < 4; j++) {
        int rr = r + j * 32;
        cpa16(sb + rr * 144 + c * 16,         g_xh + (size_t)(m0 + rr) * E_ + k0 + c * 8);
        cpa16(sb + 18432 + rr * 144 + c * 16, g_wh + (size_t)(n0 + rr) * E_ + k0 + c * 8);
    }
    cpa_commit();
}

__global__ void __launch_bounds__(256, 2) xgemm_h()
{
    extern __shared__ char sm[];
    const uint32_t smb = smem_u32(sm);

    const int tid = threadIdx.x;
    const int wid = tid >> 5, lane = tid & 31;
    const int gid = lane >> 2, tg = lane & 3;
    const int wm = wid >> 2, wn = wid & 3;
    const int m0 = blockIdx.y * 128;
    const int n0 = blockIdx.x * 128;

    uint32_t laneA[4], laneB[2];
#pragma unroll
    for (int mi = 0; mi < 4; mi++)
        laneA[mi] = (wm * 64 + mi * 16 + ((lane >> 3) & 1) * 8 + (lane & 7)) * 144
                  + (lane >> 4) * 16;
#pragma unroll
    for (int p = 0; p < 2; p++)
        laneB[p] = 18432
                 + (wn * 32 + p * 16 + (lane >> 4) * 8 + (lane & 7)) * 144
                 + ((lane >> 3) & 1) * 16;

    float acc[4][4][4];
#pragma unroll
    for (int i = 0; i < 4; i++)
#pragma unroll
        for (int j = 0; j < 4; j++)
#pragma unroll
            for (int k = 0; k < 4; k++) acc[i][j][k] = 0.f;

    p1_issue(smb, m0, n0, 0, tid);
    p1_issue(smb + P1_STAGE, m0, n0, 64, tid);

    int st = 0;
    for (int ch = 0; ch < 16; ch++) {
        if (ch < 15) cpa_wait<1>(); else cpa_wait<0>();
        __syncthreads();
        if (ch + 2 < 16) {
            int st2 = st + 2; if (st2 >= 3) st2 -= 3;
            p1_issue(smb + st2 * P1_STAGE, m0, n0, (ch + 2) * 64, tid);
        }
        const uint32_t sb = smb + st * P1_STAGE;
#pragma unroll
        for (int kk = 0; kk < 4; kk++) {
            uint32_t a[4][4], b[2][4];
#pragma unroll
            for (int mi = 0; mi < 4; mi++) ldmx4(a[mi], sb + laneA[mi] + kk * 32);
#pragma unroll
            for (int p = 0; p < 2; p++)   ldmx4(b[p],  sb + laneB[p] + kk * 32);
#pragma unroll
            for (int mi = 0; mi < 4; mi++)
#pragma unroll
                for (int ni = 0; ni < 4; ni++)
                    mma16(acc[mi][ni], a[mi], b[ni >> 1] + (ni & 1) * 2);
        }
        if (++st >= 3) st -= 3;
    }

#pragma unroll
    for (int mi = 0; mi < 4; mi++) {
        int row = m0 + wm * 64 + mi * 16 + gid;
        int b = row >> 9, t = row & (S_ - 1);
#pragma unroll
        for (int ni = 0; ni < 4; ni++) {
            int col = n0 + wn * 32 + ni * 8 + tg * 2;
            float* p0 = g_xg + ((size_t)t * B_ + b) * NG + col;
            float* p1 = g_xg + ((size_t)(t + 8) * B_ + b) * NG + col;
            *(float2*)p0 = make_float2(acc[mi][ni][0], acc[mi][ni][1]);
            *(float2*)p1 = make_float2(acc[mi][ni][2], acc[mi][ni][3]);
        }
    }
}

// ===========================================================================
// Phase 2: persistent scan, fp16 mma, full h staged per step (R7 layout).
// CTA owns 32 gate-cols. Wh fp16 [32][1032] resident; h buf [64][1032].
// 8 warps = 4(mi) x 2(ni-pair); full-K register accumulators.
// R10 deltas: flag-based grid barrier, xg prefetch, no final-step barrier.
// ===========================================================================
#define HROW   2064                       // bytes per SMEM row (1032 halves)
#define WH_OFF 0                          // 32*2064  = 66048
#define AB_OFF 66048                      // 64*2064  = 132096
#define ZB_OFF 198144                     // 64*34*4  = 8704
#define CS_OFF 206848                     // 2048
#define BS_OFF 208896                     // 128
#define P2_SMEM 209024

template<int W>
__device__ __forceinline__ void p2_group(int ksb, uint32_t aA, uint32_t aB, float acc[2][4]) {
    cpa_wait<W>();
    __syncthreads();
#pragma unroll
    for (int ks = 0; ks < 16; ks++) {
        uint32_t a[4], b[4];
        ldmx4(a, aA + (ksb + ks) * 32);
        ldmx4(b, aB + (ksb + ks) * 32);
        mma16(acc[0], a, b);
        mma16(acc[1], a, b + 2);
    }
}

__global__ void __launch_bounds__(256, 1) lstm_seq_h(
    const float* __restrict__ Wf, const float* __restrict__ bf,
    const float* __restrict__ Wi, const float* __restrict__ bi,
    const float* __restrict__ Wc, const float* __restrict__ bc,
    const float* __restrict__ Wo, const float* __restrict__ bo,
    float* __restrict__ out)
{
    extern __shared__ char sm[];
    float* zbf = (float*)(sm + ZB_OFF);
    float* csm = (float*)(sm + CS_OFF);
    float* bsm = (float*)(sm + BS_OFF);

    const int tid = threadIdx.x;
    const int wid = tid >> 5, lane = tid & 31;
    const int gid = lane >> 2, tg = lane & 3;
    const int mi = wid >> 1, nh = wid & 1;
    const int cta = blockIdx.x;
    const float* Wp[4] = {Wf, Wi, Wc, Wo};
    const float* bp[4] = {bf, bi, bc, bo};

    // one-time: Wh slice -> SMEM fp16 [32 n][1024 k] (padded rows)
    for (int idx = tid; idx < 32 * 512; idx += 256) {
        int n = idx >> 9, k2 = idx & 511;
        float2 v = *(const float2*)(Wp[n >> 3] + (size_t)(cta * 8 + (n & 7)) * 2048 + 1024 + k2 * 2);
        *(__half2*)(sm + WH_OFF + n * HROW + k2 * 4) = __floats2half2_rn(v.x, v.y);
    }
    if (tid < 32) bsm[tid] = bp[tid >> 3][cta * 8 + (tid & 7)];
    if (tid == 0) *(volatile unsigned*)&g_flags[cta * 64] = 0u;     // replay-safe reset
    for (int i = tid; i < 512; i += 256) {
        csm[i] = 0.f;
        g_hh[0][(i >> 3) * H_ + cta * 8 + (i & 7)] = __float2half(0.f);
    }
    __syncthreads();
    grid_barrier();          // atomic barrier: flag resets + h0 visible everywhere

    const uint32_t abBase = smem_u32(sm + AB_OFF);
    const uint32_t aA = abBase
        + (mi * 16 + ((lane >> 3) & 1) * 8 + (lane & 7)) * HROW + (lane >> 4) * 16;
    const uint32_t aB = smem_u32(sm + WH_OFF)
        + (nh * 16 + (lane >> 4) * 8 + (lane & 7)) * HROW + ((lane >> 3) & 1) * 16;

    for (int t = 0; t < S_; t++) {
        const __half* hcur = g_hh[t & 1];
        // stage full h (128 KB) in 4 cp.async commit groups (k quarters)
#pragma unroll
        for (int g = 0; g < 4; g++) {
#pragma unroll
            for (int j = 0; j < 8; j++) {
                int idx = tid + j * 256;
                int r = idx >> 5, c = idx & 31;
                cpa16(abBase + r * HROW + g * 512 + c * 16,
                      hcur + r * H_ + g * 256 + c * 8);
            }
            cpa_commit();
        }

        // prefetch xg for this thread's 2 epilogue elements (overlaps MMA)
        float xpf[2][4];
#pragma unroll
        for (int q = 0; q < 2; q++) {
            int i = tid + q * 256;
            int b = i >> 3, r = i & 7;
            const float* xgb = g_xg + ((size_t)t * B_ + b) * NG + cta * 8 + r;
            xpf[q][0] = __ldg(xgb);
            xpf[q][1] = __ldg(xgb + 1024);
            xpf[q][2] = __ldg(xgb + 2048);
            xpf[q][3] = __ldg(xgb + 3072);
        }

        float acc[2][4];
#pragma unroll
        for (int p = 0; p < 2; p++)
#pragma unroll
            for (int k = 0; k < 4; k++) acc[p][k] = 0.f;

        p2_group<3>(0,  aA, aB, acc);
        p2_group<2>(16, aA, aB, acc);
        p2_group<1>(32, aA, aB, acc);
        p2_group<0>(48, aA, aB, acc);

        // write z to SMEM
        const int row0 = mi * 16 + gid;
#pragma unroll
        for (int p = 0; p < 2; p++) {
            int col = (nh * 2 + p) * 8 + tg * 2;
            *(float2*)&zbf[row0 * 34 + col]       = make_float2(acc[p][0], acc[p][1]);
            *(float2*)&zbf[(row0 + 8) * 34 + col] = make_float2(acc[p][2], acc[p][3]);
        }
        __syncthreads();

        // gate math; c stays in SMEM; h -> fp16 global + fp32 output
        __half* hnext = g_hh[(t + 1) & 1];
#pragma unroll
        for (int q = 0; q < 2; q++) {
            int i = tid + q * 256;
            int b = i >> 3, r = i & 7;
            float zf = zbf[b * 34 + r]      + bsm[r]      + xpf[q][0];
            float zi = zbf[b * 34 + 8 + r]  + bsm[8 + r]  + xpf[q][1];
            float zg = zbf[b * 34 + 16 + r] + bsm[16 + r] + xpf[q][2];
            float zo = zbf[b * 34 + 24 + r] + bsm[24 + r] + xpf[q][3];
            float cc = sigm(zf) * csm[i] + sigm(zi) * tanhf(zg);
            csm[i] = cc;
            float h = sigm(zo) * tanhf(cc);
            int hc = cta * 8 + r;
            hnext[b * H_ + hc] = __float2half(h);
            out[((size_t)b * S_ + t) * H_ + hc] = h;
            if (t == S_ - 1) {
                out[(size_t)B_ * S_ * H_ + b * H_ + hc] = h;                    // hT
                out[(size_t)B_ * S_ * H_ + (size_t)B_ * H_ + b * H_ + hc] = cc; // cT
            }
        }
        if (t < S_ - 1) grid_barrier_flag(cta, (unsigned)(t + 1));
    }
}

// ===========================================================================
extern "C" void kernel_launch(void* const* d_in, const int* in_sizes, int n_in,
                              void* d_out, int out_size) {
    const float* x  = (const float*)d_in[0];
    const float* Wf = (const float*)d_in[1];
    const float* bf = (const float*)d_in[2];
    const float* Wi = (const float*)d_in[3];
    const float* bi = (const float*)d_in[4];
    const float* Wc = (const float*)d_in[5];
    const float* bc = (const float*)d_in[6];
    const float* Wo = (const float*)d_in[7];
    const float* bo = (const float*)d_in[8];
    float* out = (float*)d_out;

    convert_h<<<1024, 256>>>(x, Wf, Wi, Wc, Wo);

    cudaFuncSetAttribute(xgemm_h, cudaFuncAttributeMaxDynamicSharedMemorySize, P1_SMEM);
    dim3 g1(NG / 128, (B_ * S_) / 128);            // (32, 256)
    xgemm_h<<<g1, 256, P1_SMEM>>>();

    cudaFuncSetAttribute(lstm_seq_h, cudaFuncAttributeMaxDynamicSharedMemorySize, P2_SMEM);
    lstm_seq_h<<<NCTA, 256, P2_SMEM>>>(Wf, bf, Wi, bi, Wc, bc, Wo, bo, out);
}

// round 12
// speedup vs baseline: 1.5026x; 1.0672x over previous
#include <cuda_runtime.h>
#include <cuda_fp16.h>
#include <cstdint>
#include <cstddef>
#include <cstring>

#define B_  64
#define S_  512
#define E_  1024
#define H_  1024
#define NG  4096
#define NCTA 128

typedef unsigned long long ull;

// ---------------- device scratch ----------------
__device__ float  g_xg[(size_t)S_ * B_ * NG];     // [t][b][n] fp32
__device__ __half g_xh[(size_t)B_ * S_ * E_];     // x in fp16
__device__ __half g_wh[(size_t)NG * E_];          // Wx in fp16, [gate-major n][k]
__device__ __half g_hh[2][B_ * H_];               // hidden state fp16, [b][k]
__device__ unsigned g_bar_count = 0;
__device__ unsigned g_bar_gen   = 0;
__device__ unsigned g_flags[NCTA * 64];           // per-CTA arrival flags, 256B stride

// ---------------- helpers ----------------
__device__ __forceinline__ uint32_t smem_u32(const void* p) {
    uint32_t a;
    asm("{ .reg .u64 t; cvta.to.shared.u64 t, %1; cvt.u32.u64 %0, t; }" : "=r"(a) : "l"(p));
    return a;
}
__device__ __forceinline__ void cpa16(uint32_t saddr, const void* g) {
    asm volatile("cp.async.cg.shared.global [%0], [%1], 16;" :: "r"(saddr), "l"(g) : "memory");
}
__device__ __forceinline__ void cpa_commit() {
    asm volatile("cp.async.commit_group;" ::: "memory");
}
template<int N> __device__ __forceinline__ void cpa_wait() {
    asm volatile("cp.async.wait_group %0;" :: "n"(N) : "memory");
}
__device__ __forceinline__ void ldmx4(uint32_t* r, uint32_t addr) {
    asm volatile("ldmatrix.sync.aligned.m8n8.x4.shared.b16 {%0,%1,%2,%3}, [%4];"
        : "=r"(r[0]), "=r"(r[1]), "=r"(r[2]), "=r"(r[3]) : "r"(addr));
}
__device__ __forceinline__ void mma16(float* d, const uint32_t* a, const uint32_t* b) {
    asm("mma.sync.aligned.m16n8k16.row.col.f32.f16.f16.f32 "
        "{%0,%1,%2,%3}, {%4,%5,%6,%7}, {%8,%9}, {%0,%1,%2,%3};"
        : "+f"(d[0]), "+f"(d[1]), "+f"(d[2]), "+f"(d[3])
        : "r"(a[0]), "r"(a[1]), "r"(a[2]), "r"(a[3]), "r"(b[0]), "r"(b[1]));
}
__device__ __forceinline__ uint32_t mapa_u32(uint32_t a, uint32_t rank) {
    uint32_t r;
    asm("mapa.shared::cluster.u32 %0, %1, %2;" : "=r"(r) : "r"(a), "r"(rank));
    return r;
}
__device__ __forceinline__ void stc64(uint32_t addr, ull v) {
    asm volatile("st.shared::cluster.b64 [%0], %1;" :: "r"(addr), "l"(v) : "memory");
}
#define CLUSTER_SYNC() do { \
    asm volatile("barrier.cluster.arrive.aligned;" ::: "memory"); \
    asm volatile("barrier.cluster.wait.aligned;"   ::: "memory"); } while (0)

__device__ __forceinline__ float sigm(float z) { return 1.f / (1.f + expf(-z)); }

// Atomic barrier — used only at init (replay-safe, proven).
__device__ __forceinline__ void grid_barrier() {
    __syncthreads();
    if (threadIdx.x == 0) {
        __threadfence();
        unsigned gen = *(volatile unsigned*)&g_bar_gen;
        if (atomicAdd(&g_bar_count, 1u) == NCTA - 1) {
            atomicExch(&g_bar_count, 0u);
            __threadfence();
            atomicAdd(&g_bar_gen, 1u);
        } else {
            while (*(volatile unsigned*)&g_bar_gen == gen) __nanosleep(32);
        }
        __threadfence();
    }
    __syncthreads();
}

// Flag barrier — no atomics; distinct-address stores + MLP polling.
__device__ __forceinline__ void grid_barrier_flag(int cta, unsigned tval) {
    __syncthreads();
    if (threadIdx.x == 0) {
        __threadfence();
        *(volatile unsigned*)&g_flags[cta * 64] = tval;   // release arrival
    }
    if (threadIdx.x < 32) {
        int need = 0xF;
        const int base = threadIdx.x * 4;
        while (need) {
#pragma unroll
            for (int j = 0; j < 4; j++) {
                if (need & (1 << j)) {
                    if (*(volatile unsigned*)&g_flags[(base + j) * 64] >= tval)
                        need &= ~(1 << j);
                }
            }
            if (need) __nanosleep(32);
        }
        __threadfence();                                   // acquire
    }
    __syncthreads();
}

// ===========================================================================
// Kernel 0: convert x and Wx (x-part columns) to fp16 scratch. Unchanged.
// ===========================================================================
__global__ void convert_h(
    const float* __restrict__ x,
    const float* __restrict__ Wf, const float* __restrict__ Wi,
    const float* __restrict__ Wc, const float* __restrict__ Wo)
{
    const int stride = gridDim.x * blockDim.x;
    const int i0 = blockIdx.x * blockDim.x + threadIdx.x;
    const int NX = B_ * S_ * E_ / 2;
    for (int i = i0; i < NX; i += stride) {
        float2 v = *(const float2*)(x + (size_t)2 * i);
        ((__half2*)g_xh)[i] = __floats2half2_rn(v.x, v.y);
    }
    const int NW = NG * E_ / 2;
    for (int i = i0; i < NW; i += stride) {
        int n = i >> 9, k2 = i & 511;
        const float* Ws = (n < 1024) ? Wf : (n < 2048) ? Wi : (n < 3072) ? Wc : Wo;
        float2 v = *(const float2*)(Ws + (size_t)(n & 1023) * 2048 + k2 * 2);
        ((__half2*)g_wh)[i] = __floats2half2_rn(v.x, v.y);
    }
}

// ===========================================================================
// Phase 1: Xg = x @ Wx^T (fp16 mma, ldmatrix, cp.async 3-stage). Unchanged.
// ===========================================================================
#define P1_STAGE 36864
#define P1_SMEM  (3 * P1_STAGE)

__device__ __forceinline__ void p1_issue(uint32_t sb, int m0, int n0, int k0, int tid) {
    const int r = tid >> 3, c = tid & 7;
#pragma unroll
    for (int j = 0; j < 4; j++) {
        int rr = r + j * 32;
        cpa16(sb + rr * 144 + c * 16,         g_xh + (size_t)(m0 + rr) * E_ + k0 + c * 8);
        cpa16(sb + 18432 + rr * 144 + c * 16, g_wh + (size_t)(n0 + rr) * E_ + k0 + c * 8);
    }
    cpa_commit();
}

__global__ void __launch_bounds__(256, 2) xgemm_h()
{
    extern __shared__ char sm[];
    const uint32_t smb = smem_u32(sm);

    const int tid = threadIdx.x;
    const int wid = tid >> 5, lane = tid & 31;
    const int gid = lane >> 2, tg = lane & 3;
    const int wm = wid >> 2, wn = wid & 3;
    const int m0 = blockIdx.y * 128;
    const int n0 = blockIdx.x * 128;

    uint32_t laneA[4], laneB[2];
#pragma unroll
    for (int mi = 0; mi < 4; mi++)
        laneA[mi] = (wm * 64 + mi * 16 + ((lane >> 3) & 1) * 8 + (lane & 7)) * 144
                  + (lane >> 4) * 16;
#pragma unroll
    for (int p = 0; p < 2; p++)
        laneB[p] = 18432
                 + (wn * 32 + p * 16 + (lane >> 4) * 8 + (lane & 7)) * 144
                 + ((lane >> 3) & 1) * 16;

    float acc[4][4][4];
#pragma unroll
    for (int i = 0; i < 4; i++)
#pragma unroll
        for (int j = 0; j < 4; j++)
#pragma unroll
            for (int k = 0; k < 4; k++) acc[i][j][k] = 0.f;

    p1_issue(smb, m0, n0, 0, tid);
    p1_issue(smb + P1_STAGE, m0, n0, 64, tid);

    int st = 0;
    for (int ch = 0; ch < 16; ch++) {
        if (ch < 15) cpa_wait<1>(); else cpa_wait<0>();
        __syncthreads();
        if (ch + 2 < 16) {
            int st2 = st + 2; if (st2 >= 3) st2 -= 3;
            p1_issue(smb + st2 * P1_STAGE, m0, n0, (ch + 2) * 64, tid);
        }
        const uint32_t sb = smb + st * P1_STAGE;
#pragma unroll
        for (int kk = 0; kk < 4; kk++) {
            uint32_t a[4][4], b[2][4];
#pragma unroll
            for (int mi = 0; mi < 4; mi++) ldmx4(a[mi], sb + laneA[mi] + kk * 32);
#pragma unroll
            for (int p = 0; p < 2; p++)   ldmx4(b[p],  sb + laneB[p] + kk * 32);
#pragma unroll
            for (int mi = 0; mi < 4; mi++)
#pragma unroll
                for (int ni = 0; ni < 4; ni++)
                    mma16(acc[mi][ni], a[mi], b[ni >> 1] + (ni & 1) * 2);
        }
        if (++st >= 3) st -= 3;
    }

#pragma unroll
    for (int mi = 0; mi < 4; mi++) {
        int row = m0 + wm * 64 + mi * 16 + gid;
        int b = row >> 9, t = row & (S_ - 1);
#pragma unroll
        for (int ni = 0; ni < 4; ni++) {
            int col = n0 + wn * 32 + ni * 8 + tg * 2;
            float* p0 = g_xg + ((size_t)t * B_ + b) * NG + col;
            float* p1 = g_xg + ((size_t)(t + 8) * B_ + b) * NG + col;
            *(float2*)p0 = make_float2(acc[mi][ni][0], acc[mi][ni][1]);
            *(float2*)p1 = make_float2(acc[mi][ni][2], acc[mi][ni][3]);
        }
    }
}

// ===========================================================================
// Phase 2: persistent scan, fp16 mma, CLUSTER-PAIR K-SPLIT.
// 64 clusters x 2 CTAs. CTA (rank = cta&1) reads only its K-half of h
// (64 KB), computes N=64 gate-cols (own 32 + partner 32) over K=512,
// sends partner-col partials via DSMEM, one cluster.sync, epilogue adds
// local + partner partials. 8 warps = 4(mi: batch16) x 2(ns: col32).
// ===========================================================================
#define HROW2   1040                      // 512 halves + 16B pad
#define WH_OFF  0                         // 64*1040 = 66560
#define AB_OFF  66560                     // 64*1040 = 66560  -> 133120
#define RED_OFF 133120                    // [64][34] f32 = 8704 -> 141824
#define ZB_OFF  141824                    // [64][34] f32 = 8704 -> 150528
#define CS_OFF  150528                    // 2048 -> 152576
#define BS_OFF  152576                    // 128  -> 152704
#define P2_SMEM 152704

__global__ void __launch_bounds__(256, 1) __cluster_dims__(2, 1, 1) lstm_seq_h(
    const float* __restrict__ Wf, const float* __restrict__ bf,
    const float* __restrict__ Wi, const float* __restrict__ bi,
    const float* __restrict__ Wc, const float* __restrict__ bc,
    const float* __restrict__ Wo, const float* __restrict__ bo,
    float* __restrict__ out)
{
    extern __shared__ char sm[];
    float* red = (float*)(sm + RED_OFF);
    float* zbf = (float*)(sm + ZB_OFF);
    float* csm = (float*)(sm + CS_OFF);
    float* bsm = (float*)(sm + BS_OFF);

    const int tid = threadIdx.x;
    const int wid = tid >> 5, lane = tid & 31;
    const int gid = lane >> 2, tg = lane & 3;
    const int mi = wid >> 1, ns = wid & 1;
    const int cta = blockIdx.x;
    const int krank = cta & 1;                  // cluster rank == K-half
    const int pcta = cta ^ 1;
    const float* Wp[4] = {Wf, Wi, Wc, Wo};
    const float* bp[4] = {bf, bi, bc, bo};

    // one-time: Wh -> SMEM fp16. rows 0-31 = own cols, 32-63 = partner cols;
    // each row holds this CTA's K-half (512 halves).
    for (int idx = tid; idx < 64 * 256; idx += 256) {
        int n = idx >> 8, k2 = idx & 255;
        int colset = (n < 32) ? cta : pcta;
        int nn = n & 31;
        const float* wr = Wp[nn >> 3]
            + (size_t)(colset * 8 + (nn & 7)) * 2048 + 1024 + krank * 512 + k2 * 2;
        float2 v = *(const float2*)wr;
        *(__half2*)(sm + WH_OFF + n * HROW2 + k2 * 4) = __floats2half2_rn(v.x, v.y);
    }
    if (tid < 32) bsm[tid] = bp[tid >> 3][cta * 8 + (tid & 7)];
    if (tid == 0) *(volatile unsigned*)&g_flags[cta * 64] = 0u;
    for (int i = tid; i < 512; i += 256) {
        csm[i] = 0.f;
        g_hh[0][(i >> 3) * H_ + cta * 8 + (i & 7)] = __float2half(0.f);
    }
    __syncthreads();
    grid_barrier();

    const uint32_t abBase = smem_u32(sm + AB_OFF);
    const uint32_t whBase = smem_u32(sm + WH_OFF);
    const uint32_t aA = abBase
        + (mi * 16 + ((lane >> 3) & 1) * 8 + (lane & 7)) * HROW2 + (lane >> 4) * 16;
    uint32_t laneB[2];
#pragma unroll
    for (int p = 0; p < 2; p++)
        laneB[p] = whBase
            + (ns * 32 + p * 16 + (lane >> 4) * 8 + (lane & 7)) * HROW2
            + ((lane >> 3) & 1) * 16;
    const uint32_t peer_red = mapa_u32(smem_u32(red), (uint32_t)(krank ^ 1));

    for (int t = 0; t < S_; t++) {
        const __half* hcur = g_hh[t & 1];
        // stage my K-half of h (64 KB) in 2 cp.async commit groups
#pragma unroll
        for (int g = 0; g < 2; g++) {
#pragma unroll
            for (int j = 0; j < 8; j++) {
                int idx = tid + j * 256;
                int r = idx >> 5, c = idx & 31;
                cpa16(abBase + r * HROW2 + g * 512 + c * 16,
                      hcur + r * H_ + krank * 512 + g * 256 + c * 8);
            }
            cpa_commit();
        }

        // prefetch xg (overlaps MMA)
        float xpf[2][4];
#pragma unroll
        for (int q = 0; q < 2; q++) {
            int i = tid + q * 256;
            int b = i >> 3, r = i & 7;
            const float* xgb = g_xg + ((size_t)t * B_ + b) * NG + cta * 8 + r;
            xpf[q][0] = __ldg(xgb);
            xpf[q][1] = __ldg(xgb + 1024);
            xpf[q][2] = __ldg(xgb + 2048);
            xpf[q][3] = __ldg(xgb + 3072);
        }

        float acc[4][4];
#pragma unroll
        for (int i = 0; i < 4; i++)
#pragma unroll
            for (int k = 0; k < 4; k++) acc[i][k] = 0.f;

#pragma unroll
        for (int g = 0; g < 2; g++) {
            if (g == 0) cpa_wait<1>(); else cpa_wait<0>();
            __syncthreads();
#pragma unroll
            for (int ksl = 0; ksl < 16; ksl++) {
                const uint32_t koff = (uint32_t)(g * 16 + ksl) * 32;
                uint32_t a[4], b0[4], b1[4];
                ldmx4(a,  aA + koff);
                ldmx4(b0, laneB[0] + koff);
                ldmx4(b1, laneB[1] + koff);
                mma16(acc[0], a, b0);
                mma16(acc[1], a, b0 + 2);
                mma16(acc[2], a, b1);
                mma16(acc[3], a, b1 + 2);
            }
        }

        // partials: ns=0 -> local zbf (own cols); ns=1 -> DSMEM to peer red
        const int b0r = mi * 16 + gid;
        if (ns == 0) {
#pragma unroll
            for (int nt = 0; nt < 4; nt++) {
                int col = nt * 8 + tg * 2;
                *(float2*)&zbf[b0r * 34 + col]       = make_float2(acc[nt][0], acc[nt][1]);
                *(float2*)&zbf[(b0r + 8) * 34 + col] = make_float2(acc[nt][2], acc[nt][3]);
            }
        } else {
#pragma unroll
            for (int nt = 0; nt < 4; nt++) {
                int col = nt * 8 + tg * 2;
                float2 f0 = make_float2(acc[nt][0], acc[nt][1]);
                float2 f1 = make_float2(acc[nt][2], acc[nt][3]);
                ull v0, v1;
                memcpy(&v0, &f0, 8);
                memcpy(&v1, &f1, 8);
                stc64(peer_red + (uint32_t)(b0r * 34 + col) * 4, v0);
                stc64(peer_red + (uint32_t)((b0r + 8) * 34 + col) * 4, v1);
            }
        }
        CLUSTER_SYNC();

        // gate math; c stays in SMEM; h -> fp16 global + fp32 output
        __half* hnext = g_hh[(t + 1) & 1];
#pragma unroll
        for (int q = 0; q < 2; q++) {
            int i = tid + q * 256;
            int b = i >> 3, r = i & 7;
            float zf = zbf[b * 34 + r]      + red[b * 34 + r]      + bsm[r]      + xpf[q][0];
            float zi = zbf[b * 34 + 8 + r]  + red[b * 34 + 8 + r]  + bsm[8 + r]  + xpf[q][1];
            float zg = zbf[b * 34 + 16 + r] + red[b * 34 + 16 + r] + bsm[16 + r] + xpf[q][2];
            float zo = zbf[b * 34 + 24 + r] + red[b * 34 + 24 + r] + bsm[24 + r] + xpf[q][3];
            float cc = sigm(zf) * csm[i] + sigm(zi) * tanhf(zg);
            csm[i] = cc;
            float h = sigm(zo) * tanhf(cc);
            int hc = cta * 8 + r;
            hnext[b * H_ + hc] = __float2half(h);
            out[((size_t)b * S_ + t) * H_ + hc] = h;
            if (t == S_ - 1) {
                out[(size_t)B_ * S_ * H_ + b * H_ + hc] = h;                    // hT
                out[(size_t)B_ * S_ * H_ + (size_t)B_ * H_ + b * H_ + hc] = cc; // cT
            }
        }
        if (t < S_ - 1) grid_barrier_flag(cta, (unsigned)(t + 1));
    }
}

// ===========================================================================
extern "C" void kernel_launch(void* const* d_in, const int* in_sizes, int n_in,
                              void* d_out, int out_size) {
    const float* x  = (const float*)d_in[0];
    const float* Wf = (const float*)d_in[1];
    const float* bf = (const float*)d_in[2];
    const float* Wi = (const float*)d_in[3];
    const float* bi = (const float*)d_in[4];
    const float* Wc = (const float*)d_in[5];
    const float* bc = (const float*)d_in[6];
    const float* Wo = (const float*)d_in[7];
    const float* bo = (const float*)d_in[8];
    float* out = (float*)d_out;

    convert_h<<<1024, 256>>>(x, Wf, Wi, Wc, Wo);

    cudaFuncSetAttribute(xgemm_h, cudaFuncAttributeMaxDynamicSharedMemorySize, P1_SMEM);
    dim3 g1(NG / 128, (B_ * S_) / 128);            // (32, 256)
    xgemm_h<<<g1, 256, P1_SMEM>>>();

    cudaFuncSetAttribute(lstm_seq_h, cudaFuncAttributeMaxDynamicSharedMemorySize, P2_SMEM);
    lstm_seq_h<<<NCTA, 256, P2_SMEM>>>(Wf, bf, Wi, bi, Wc, bc, Wo, bo, out);
}